// round 4
// baseline (speedup 1.0000x reference)
#include <cuda_runtime.h>
#include <math.h>

#define TOTAL  2048
#define HIDDEN 1024
#define NHEAD  16
#define DH     64
#define NSEG   8
#define NCU    9

// Scratch (static device arrays — no allocation inside kernel_launch).
__device__ __align__(256) float g_q[TOTAL * HIDDEN];
__device__ __align__(256) float g_k[TOTAL * HIDDEN];
__device__ __align__(256) float g_v[TOTAL * HIDDEN];
__device__ __align__(256) float g_ctx[TOTAL * HIDDEN];
__device__ __align__(256) float g_S[(size_t)NHEAD * TOTAL * TOTAL];   // 256 MB scores scratch

__device__ __forceinline__ int segid_of(const int* scu, int t) {
    int s = 0;
    #pragma unroll
    for (int i = 0; i < NSEG - 1; i++) {
        if (scu[s + 1] <= t) s++;
    }
    return s;
}

// ---------------------------------------------------------------------------
// C[M,N] = A[M,K] @ B[N,K]^T + bias[N]   (both A and B are K-major / row-major)
// 128x128 tile, BK=8, 256 threads, 8x8 per thread.
// ---------------------------------------------------------------------------
__global__ void __launch_bounds__(256) gemm_nt_bias(
    const float* __restrict__ A, const float* __restrict__ B,
    const float* __restrict__ bias, float* __restrict__ C,
    int M, int N, int K)
{
    __shared__ __align__(16) float As[8][128];
    __shared__ __align__(16) float Bs[8][128];

    const int tid  = threadIdx.x;
    const int row0 = blockIdx.y * 128;
    const int col0 = blockIdx.x * 128;
    const int tr   = tid >> 4;   // 0..15
    const int tc   = tid & 15;   // 0..15

    const int aRow = tid >> 1;          // 0..127
    const int aK4  = (tid & 1) * 4;     // 0 or 4

    const float* Aptr = A + (size_t)(row0 + aRow) * K + aK4;
    const float* Bptr = B + (size_t)(col0 + aRow) * K + aK4;

    float acc[8][8];
    #pragma unroll
    for (int i = 0; i < 8; i++)
        #pragma unroll
        for (int j = 0; j < 8; j++) acc[i][j] = 0.f;

    for (int k0 = 0; k0 < K; k0 += 8) {
        float4 av = *(const float4*)(Aptr + k0);
        float4 bv = *(const float4*)(Bptr + k0);
        __syncthreads();
        As[aK4 + 0][aRow] = av.x; As[aK4 + 1][aRow] = av.y;
        As[aK4 + 2][aRow] = av.z; As[aK4 + 3][aRow] = av.w;
        Bs[aK4 + 0][aRow] = bv.x; Bs[aK4 + 1][aRow] = bv.y;
        Bs[aK4 + 2][aRow] = bv.z; Bs[aK4 + 3][aRow] = bv.w;
        __syncthreads();

        #pragma unroll
        for (int kk = 0; kk < 8; kk++) {
            float4 a0 = *(const float4*)&As[kk][tr * 8];
            float4 a1 = *(const float4*)&As[kk][tr * 8 + 4];
            float4 b0 = *(const float4*)&Bs[kk][tc * 8];
            float4 b1 = *(const float4*)&Bs[kk][tc * 8 + 4];
            float ra[8] = {a0.x, a0.y, a0.z, a0.w, a1.x, a1.y, a1.z, a1.w};
            float rb[8] = {b0.x, b0.y, b0.z, b0.w, b1.x, b1.y, b1.z, b1.w};
            #pragma unroll
            for (int i = 0; i < 8; i++)
                #pragma unroll
                for (int j = 0; j < 8; j++)
                    acc[i][j] = fmaf(ra[i], rb[j], acc[i][j]);
        }
    }

    #pragma unroll
    for (int i = 0; i < 8; i++) {
        int r = row0 + tr * 8 + i;
        #pragma unroll
        for (int j = 0; j < 8; j++) {
            int c = col0 + tc * 8 + j;
            C[(size_t)r * N + c] = acc[i][j] + bias[c];
        }
    }
}

// ---------------------------------------------------------------------------
// Scores: S[h][q][k] = (q_h . k_h) * scale for same-seg pairs, -1e30 otherwise.
// Only 64x64 tiles that intersect the segment union of the query tile run.
// ---------------------------------------------------------------------------
__global__ void __launch_bounds__(256) scores_kernel(
    const float* __restrict__ q, const float* __restrict__ k,
    const int* __restrict__ cu, float* __restrict__ S)
{
    const int h  = blockIdx.z;
    const int q0 = blockIdx.y * 64;
    const int k0 = blockIdx.x * 64;

    __shared__ __align__(16) int   scu[NCU];
    __shared__ __align__(16) int   qseg[64], kseg[64];
    __shared__ __align__(16) float Qs[64][65];
    __shared__ __align__(16) float Ks[64][65];

    const int tid = threadIdx.x;
    if (tid < NCU) scu[tid] = cu[tid];
    __syncthreads();

    const int s_lo = segid_of(scu, q0);
    const int s_hi = segid_of(scu, q0 + 63);
    const int ustart = scu[s_lo];
    const int uend   = scu[s_hi + 1];
    if (k0 + 64 <= ustart || k0 >= uend) return;   // tile fully masked

    if (tid < 64)       qseg[tid]      = segid_of(scu, q0 + tid);
    else if (tid < 128) kseg[tid - 64] = segid_of(scu, k0 + tid - 64);

    #pragma unroll
    for (int l = 0; l < 4; l++) {
        int fi = tid + l * 256;          // float4 index, 0..1023
        int r  = fi >> 4;
        int c4 = (fi & 15) << 2;
        float4 vq = *(const float4*)(q + (size_t)(q0 + r) * HIDDEN + h * DH + c4);
        Qs[r][c4 + 0] = vq.x; Qs[r][c4 + 1] = vq.y;
        Qs[r][c4 + 2] = vq.z; Qs[r][c4 + 3] = vq.w;
        float4 vk = *(const float4*)(k + (size_t)(k0 + r) * HIDDEN + h * DH + c4);
        Ks[r][c4 + 0] = vk.x; Ks[r][c4 + 1] = vk.y;
        Ks[r][c4 + 2] = vk.z; Ks[r][c4 + 3] = vk.w;
    }
    __syncthreads();

    const int qb = (tid >> 4) * 4;
    const int kb = (tid & 15) * 4;
    float acc[4][4];
    #pragma unroll
    for (int i = 0; i < 4; i++)
        #pragma unroll
        for (int j = 0; j < 4; j++) acc[i][j] = 0.f;

    #pragma unroll 8
    for (int d = 0; d < 64; d++) {
        float rq[4], rk[4];
        #pragma unroll
        for (int i = 0; i < 4; i++) rq[i] = Qs[qb + i][d];
        #pragma unroll
        for (int j = 0; j < 4; j++) rk[j] = Ks[kb + j][d];
        #pragma unroll
        for (int i = 0; i < 4; i++)
            #pragma unroll
            for (int j = 0; j < 4; j++)
                acc[i][j] = fmaf(rq[i], rk[j], acc[i][j]);
    }

    const float scale = 0.125f;   // 1/sqrt(64)
    #pragma unroll
    for (int i = 0; i < 4; i++) {
        int qs_ = qseg[qb + i];
        size_t rowbase = ((size_t)h * TOTAL + (q0 + qb + i)) * TOTAL;
        #pragma unroll
        for (int j = 0; j < 4; j++) {
            float val = (qs_ == kseg[kb + j]) ? acc[i][j] * scale : -1e30f;
            S[rowbase + (k0 + kb + j)] = val;
        }
    }
}

// ---------------------------------------------------------------------------
// Row softmax over [seg_start, seg_end) only.
// ---------------------------------------------------------------------------
__global__ void __launch_bounds__(128) softmax_kernel(
    const int* __restrict__ cu, float* __restrict__ S)
{
    const int qi = blockIdx.x;
    const int h  = blockIdx.y;
    __shared__ __align__(16) int   scu[NCU];
    __shared__ __align__(16) float redmax[4], redsum[4];

    const int tid = threadIdx.x;
    if (tid < NCU) scu[tid] = cu[tid];
    __syncthreads();

    const int s  = segid_of(scu, qi);
    const int qs = scu[s], qe = scu[s + 1];
    const int len = qe - qs;
    float* row = S + ((size_t)h * TOTAL + qi) * TOTAL + qs;

    float v[16];
    const int n = (len + 127) >> 7;
    float m = -1e30f;
    for (int i = 0; i < n; i++) {
        int idx = i * 128 + tid;
        v[i] = (idx < len) ? row[idx] : -1e30f;
        m = fmaxf(m, v[i]);
    }
    #pragma unroll
    for (int off = 16; off; off >>= 1)
        m = fmaxf(m, __shfl_xor_sync(0xffffffffu, m, off));
    if ((tid & 31) == 0) redmax[tid >> 5] = m;
    __syncthreads();
    m = fmaxf(fmaxf(redmax[0], redmax[1]), fmaxf(redmax[2], redmax[3]));

    float sum = 0.f;
    for (int i = 0; i < n; i++) {
        int idx = i * 128 + tid;
        v[i] = (idx < len) ? __expf(v[i] - m) : 0.f;
        sum += v[i];
    }
    #pragma unroll
    for (int off = 16; off; off >>= 1)
        sum += __shfl_xor_sync(0xffffffffu, sum, off);
    if ((tid & 31) == 0) redsum[tid >> 5] = sum;
    __syncthreads();
    sum = redsum[0] + redsum[1] + redsum[2] + redsum[3];

    const float inv = 1.0f / sum;
    for (int i = 0; i < n; i++) {
        int idx = i * 128 + tid;
        if (idx < len) row[idx] = v[i] * inv;
    }
}

// ---------------------------------------------------------------------------
// ctx[q, h*64+d] = sum_k P[h][q][k] * V[k, h*64+d], k restricted to q's segment.
// ---------------------------------------------------------------------------
__global__ void __launch_bounds__(256) pv_kernel(
    const float* __restrict__ S, const float* __restrict__ v,
    const int* __restrict__ cu, float* __restrict__ ctx)
{
    const int h  = blockIdx.y;
    const int q0 = blockIdx.x * 64;

    __shared__ __align__(16) int   scu[NCU];
    __shared__ __align__(16) int   qseg[64], kseg[32];
    __shared__ __align__(16) float Ps[64][33];
    __shared__ __align__(16) float Vs[32][64];

    const int tid = threadIdx.x;
    if (tid < NCU) scu[tid] = cu[tid];
    __syncthreads();

    if (tid < 64) qseg[tid] = segid_of(scu, q0 + tid);
    const int s_lo = segid_of(scu, q0);
    const int s_hi = segid_of(scu, q0 + 63);
    const int ustart = scu[s_lo];
    const int uend   = scu[s_hi + 1];

    const int qb = (tid >> 4) * 4;
    const int db = (tid & 15) * 4;
    float acc[4][4];
    #pragma unroll
    for (int i = 0; i < 4; i++)
        #pragma unroll
        for (int j = 0; j < 4; j++) acc[i][j] = 0.f;

    for (int kb = (ustart / 32) * 32; kb < uend; kb += 32) {
        __syncthreads();                      // protect kseg/Ps/Vs from prev iter readers
        if (tid < 32) kseg[tid] = segid_of(scu, kb + tid);
        __syncthreads();

        #pragma unroll
        for (int l = 0; l < 2; l++) {
            int fi = tid + l * 256;           // 0..511 float4
            int r  = fi >> 3;
            int c4 = (fi & 7) << 2;
            float4 p4 = *(const float4*)(S + ((size_t)h * TOTAL + (q0 + r)) * TOTAL + kb + c4);
            int qg = qseg[r];
            Ps[r][c4 + 0] = (kseg[c4 + 0] == qg) ? p4.x : 0.f;
            Ps[r][c4 + 1] = (kseg[c4 + 1] == qg) ? p4.y : 0.f;
            Ps[r][c4 + 2] = (kseg[c4 + 2] == qg) ? p4.z : 0.f;
            Ps[r][c4 + 3] = (kseg[c4 + 3] == qg) ? p4.w : 0.f;
        }
        #pragma unroll
        for (int l = 0; l < 2; l++) {
            int fi = tid + l * 256;
            int r  = fi >> 4;
            int c4 = (fi & 15) << 2;
            *(float4*)&Vs[r][c4] =
                *(const float4*)(v + (size_t)(kb + r) * HIDDEN + h * DH + c4);
        }
        __syncthreads();

        #pragma unroll 8
        for (int kk = 0; kk < 32; kk++) {
            float4 rv = *(const float4*)&Vs[kk][db];
            float rp[4];
            #pragma unroll
            for (int i = 0; i < 4; i++) rp[i] = Ps[qb + i][kk];
            #pragma unroll
            for (int i = 0; i < 4; i++) {
                acc[i][0] = fmaf(rp[i], rv.x, acc[i][0]);
                acc[i][1] = fmaf(rp[i], rv.y, acc[i][1]);
                acc[i][2] = fmaf(rp[i], rv.z, acc[i][2]);
                acc[i][3] = fmaf(rp[i], rv.w, acc[i][3]);
            }
        }
    }

    #pragma unroll
    for (int i = 0; i < 4; i++)
        #pragma unroll
        for (int j = 0; j < 4; j++)
            ctx[(size_t)(q0 + qb + i) * HIDDEN + h * DH + db + j] = acc[i][j];
}

// ---------------------------------------------------------------------------
extern "C" void kernel_launch(void* const* d_in, const int* in_sizes, int n_in,
                              void* d_out, int out_size)
{
    (void)in_sizes; (void)n_in; (void)out_size;
    const float* x  = (const float*)d_in[0];
    const int*   cu = (const int*)d_in[1];
    const float* Wq = (const float*)d_in[2];
    const float* bq = (const float*)d_in[3];
    const float* Wk = (const float*)d_in[4];
    const float* bk = (const float*)d_in[5];
    const float* Wv = (const float*)d_in[6];
    const float* bv = (const float*)d_in[7];
    const float* Wo = (const float*)d_in[8];
    const float* bo = (const float*)d_in[9];
    float* out = (float*)d_out;

    float *q, *k, *v, *ctx, *S;
    cudaGetSymbolAddress((void**)&q,   g_q);
    cudaGetSymbolAddress((void**)&k,   g_k);
    cudaGetSymbolAddress((void**)&v,   g_v);
    cudaGetSymbolAddress((void**)&ctx, g_ctx);
    cudaGetSymbolAddress((void**)&S,   g_S);

    dim3 gGrid(HIDDEN / 128, TOTAL / 128);   // (8, 16)
    gemm_nt_bias<<<gGrid, 256>>>(x, Wq, bq, q, TOTAL, HIDDEN, HIDDEN);
    gemm_nt_bias<<<gGrid, 256>>>(x, Wk, bk, k, TOTAL, HIDDEN, HIDDEN);
    gemm_nt_bias<<<gGrid, 256>>>(x, Wv, bv, v, TOTAL, HIDDEN, HIDDEN);

    dim3 sGrid(TOTAL / 64, TOTAL / 64, NHEAD);   // (32, 32, 16)
    scores_kernel<<<sGrid, 256>>>(q, k, cu, S);

    softmax_kernel<<<dim3(TOTAL, NHEAD), 128>>>(cu, S);

    pv_kernel<<<dim3(TOTAL / 64, NHEAD), 256>>>(S, v, cu, ctx);

    gemm_nt_bias<<<gGrid, 256>>>(ctx, Wo, bo, out, TOTAL, HIDDEN, HIDDEN);
}

// round 5
// speedup vs baseline: 1.8823x; 1.8823x over previous
#include <cuda_runtime.h>
#include <math.h>
#include <stdint.h>

#define TOTAL  2048
#define HIDDEN 1024
#define NHEAD  16
#define DH     64
#define NSEG   8
#define NCU    9

// Scratch (static device arrays — no allocation inside kernel_launch).
__device__ __align__(256) float g_q[TOTAL * HIDDEN];
__device__ __align__(256) float g_k[TOTAL * HIDDEN];
__device__ __align__(256) float g_v[TOTAL * HIDDEN];
__device__ __align__(256) float g_ctx[TOTAL * HIDDEN];
__device__ __align__(256) float g_S[(size_t)NHEAD * TOTAL * TOTAL];   // 256 MB scores scratch

__device__ __forceinline__ int segid_of(const int* scu, int t) {
    int s = 0;
    #pragma unroll
    for (int i = 0; i < NSEG - 1; i++) {
        if (scu[s + 1] <= t) s++;
    }
    return s;
}

__device__ __forceinline__ uint32_t f2tf32(float f) {
    uint32_t u;
    asm("cvt.rna.tf32.f32 %0, %1;" : "=r"(u) : "f"(f));
    return u;
}

__device__ __forceinline__ void mma_tf32(
    float& d0, float& d1, float& d2, float& d3,
    uint32_t a0, uint32_t a1, uint32_t a2, uint32_t a3,
    uint32_t b0, uint32_t b1)
{
    asm volatile(
        "mma.sync.aligned.m16n8k8.row.col.f32.tf32.tf32.f32 "
        "{%0,%1,%2,%3}, {%4,%5,%6,%7}, {%8,%9}, {%0,%1,%2,%3};"
        : "+f"(d0), "+f"(d1), "+f"(d2), "+f"(d3)
        : "r"(a0), "r"(a1), "r"(a2), "r"(a3), "r"(b0), "r"(b1));
}

// ---------------------------------------------------------------------------
// C[M,N] = A[M,K] @ B[N,K]^T + bias[N] using tf32 tensor cores.
// 128x128 block tile, BK=16, 256 threads (8 warps: 2 in M x 4 in N),
// each warp computes 64x32 via 4x4 tiles of mma.m16n8k8.
// M, N, K must be multiples of 128/128/16 (true for all four calls here).
// ---------------------------------------------------------------------------
__global__ void __launch_bounds__(256) gemm_tf32_nt_bias(
    const float* __restrict__ A, const float* __restrict__ B,
    const float* __restrict__ bias, float* __restrict__ C,
    int M, int N, int K)
{
    __shared__ __align__(16) float As[128][20];   // [m][k], pad 20 => conflict-free frag loads
    __shared__ __align__(16) float Bs[128][20];   // [n][k]

    const int tid  = threadIdx.x;
    const int lane = tid & 31;
    const int wid  = tid >> 5;
    const int wm   = (wid & 1) * 64;   // warp M offset in tile
    const int wn   = (wid >> 1) * 32;  // warp N offset in tile
    const int row0 = blockIdx.y * 128;
    const int col0 = blockIdx.x * 128;

    const int g  = lane >> 2;   // 0..7 (group id)
    const int t4 = lane & 3;    // 0..3

    float acc[4][4][4];
    #pragma unroll
    for (int i = 0; i < 4; i++)
        #pragma unroll
        for (int j = 0; j < 4; j++)
            #pragma unroll
            for (int f = 0; f < 4; f++) acc[i][j][f] = 0.f;

    const int lr = tid >> 2;         // 0..63 — loads rows lr and lr+64
    const int lk = (tid & 3) << 2;   // 0,4,8,12

    const float* Arow0 = A + (size_t)(row0 + lr) * K + lk;
    const float* Arow1 = A + (size_t)(row0 + lr + 64) * K + lk;
    const float* Brow0 = B + (size_t)(col0 + lr) * K + lk;
    const float* Brow1 = B + (size_t)(col0 + lr + 64) * K + lk;

    for (int k0 = 0; k0 < K; k0 += 16) {
        float4 a0v = *(const float4*)(Arow0 + k0);
        float4 a1v = *(const float4*)(Arow1 + k0);
        float4 b0v = *(const float4*)(Brow0 + k0);
        float4 b1v = *(const float4*)(Brow1 + k0);
        __syncthreads();
        {
            float4 s;
            s.x = __uint_as_float(f2tf32(a0v.x)); s.y = __uint_as_float(f2tf32(a0v.y));
            s.z = __uint_as_float(f2tf32(a0v.z)); s.w = __uint_as_float(f2tf32(a0v.w));
            *(float4*)&As[lr][lk] = s;
            s.x = __uint_as_float(f2tf32(a1v.x)); s.y = __uint_as_float(f2tf32(a1v.y));
            s.z = __uint_as_float(f2tf32(a1v.z)); s.w = __uint_as_float(f2tf32(a1v.w));
            *(float4*)&As[lr + 64][lk] = s;
            s.x = __uint_as_float(f2tf32(b0v.x)); s.y = __uint_as_float(f2tf32(b0v.y));
            s.z = __uint_as_float(f2tf32(b0v.z)); s.w = __uint_as_float(f2tf32(b0v.w));
            *(float4*)&Bs[lr][lk] = s;
            s.x = __uint_as_float(f2tf32(b1v.x)); s.y = __uint_as_float(f2tf32(b1v.y));
            s.z = __uint_as_float(f2tf32(b1v.z)); s.w = __uint_as_float(f2tf32(b1v.w));
            *(float4*)&Bs[lr + 64][lk] = s;
        }
        __syncthreads();

        #pragma unroll
        for (int kk = 0; kk < 16; kk += 8) {
            uint32_t af[4][4];
            #pragma unroll
            for (int mi = 0; mi < 4; mi++) {
                int r = wm + mi * 16;
                af[mi][0] = __float_as_uint(As[r + g     ][kk + t4    ]);
                af[mi][1] = __float_as_uint(As[r + g + 8 ][kk + t4    ]);
                af[mi][2] = __float_as_uint(As[r + g     ][kk + t4 + 4]);
                af[mi][3] = __float_as_uint(As[r + g + 8 ][kk + t4 + 4]);
            }
            uint32_t bf[4][2];
            #pragma unroll
            for (int ni = 0; ni < 4; ni++) {
                int n = wn + ni * 8;
                bf[ni][0] = __float_as_uint(Bs[n + g][kk + t4    ]);
                bf[ni][1] = __float_as_uint(Bs[n + g][kk + t4 + 4]);
            }
            #pragma unroll
            for (int mi = 0; mi < 4; mi++)
                #pragma unroll
                for (int ni = 0; ni < 4; ni++)
                    mma_tf32(acc[mi][ni][0], acc[mi][ni][1], acc[mi][ni][2], acc[mi][ni][3],
                             af[mi][0], af[mi][1], af[mi][2], af[mi][3],
                             bf[ni][0], bf[ni][1]);
        }
    }

    // Epilogue: c0: (row=g, col=2*t4), c1: col+1, c2: row+8, c3: row+8,col+1
    #pragma unroll
    for (int ni = 0; ni < 4; ni++) {
        int c = col0 + wn + ni * 8 + 2 * t4;
        float2 bv = *(const float2*)(bias + c);
        #pragma unroll
        for (int mi = 0; mi < 4; mi++) {
            int r = row0 + wm + mi * 16 + g;
            float2 v0 = make_float2(acc[mi][ni][0] + bv.x, acc[mi][ni][1] + bv.y);
            float2 v1 = make_float2(acc[mi][ni][2] + bv.x, acc[mi][ni][3] + bv.y);
            *(float2*)(C + (size_t)r * N + c)       = v0;
            *(float2*)(C + (size_t)(r + 8) * N + c) = v1;
        }
    }
}

// ---------------------------------------------------------------------------
// Scores: S[h][q][k] = (q_h . k_h) * scale for same-seg pairs, -1e30 otherwise.
// ---------------------------------------------------------------------------
__global__ void __launch_bounds__(256) scores_kernel(
    const float* __restrict__ q, const float* __restrict__ k,
    const int* __restrict__ cu, float* __restrict__ S)
{
    const int h  = blockIdx.z;
    const int q0 = blockIdx.y * 64;
    const int k0 = blockIdx.x * 64;

    __shared__ __align__(16) int   scu[NCU];
    __shared__ __align__(16) int   qseg[64], kseg[64];
    __shared__ __align__(16) float Qs[64][65];
    __shared__ __align__(16) float Ks[64][65];

    const int tid = threadIdx.x;
    if (tid < NCU) scu[tid] = cu[tid];
    __syncthreads();

    const int s_lo = segid_of(scu, q0);
    const int s_hi = segid_of(scu, q0 + 63);
    const int ustart = scu[s_lo];
    const int uend   = scu[s_hi + 1];
    if (k0 + 64 <= ustart || k0 >= uend) return;   // tile fully masked

    if (tid < 64)       qseg[tid]      = segid_of(scu, q0 + tid);
    else if (tid < 128) kseg[tid - 64] = segid_of(scu, k0 + tid - 64);

    #pragma unroll
    for (int l = 0; l < 4; l++) {
        int fi = tid + l * 256;
        int r  = fi >> 4;
        int c4 = (fi & 15) << 2;
        float4 vq = *(const float4*)(q + (size_t)(q0 + r) * HIDDEN + h * DH + c4);
        Qs[r][c4 + 0] = vq.x; Qs[r][c4 + 1] = vq.y;
        Qs[r][c4 + 2] = vq.z; Qs[r][c4 + 3] = vq.w;
        float4 vk = *(const float4*)(k + (size_t)(k0 + r) * HIDDEN + h * DH + c4);
        Ks[r][c4 + 0] = vk.x; Ks[r][c4 + 1] = vk.y;
        Ks[r][c4 + 2] = vk.z; Ks[r][c4 + 3] = vk.w;
    }
    __syncthreads();

    const int qb = (tid >> 4) * 4;
    const int kb = (tid & 15) * 4;
    float acc[4][4];
    #pragma unroll
    for (int i = 0; i < 4; i++)
        #pragma unroll
        for (int j = 0; j < 4; j++) acc[i][j] = 0.f;

    #pragma unroll 8
    for (int d = 0; d < 64; d++) {
        float rq[4], rk[4];
        #pragma unroll
        for (int i = 0; i < 4; i++) rq[i] = Qs[qb + i][d];
        #pragma unroll
        for (int j = 0; j < 4; j++) rk[j] = Ks[kb + j][d];
        #pragma unroll
        for (int i = 0; i < 4; i++)
            #pragma unroll
            for (int j = 0; j < 4; j++)
                acc[i][j] = fmaf(rq[i], rk[j], acc[i][j]);
    }

    const float scale = 0.125f;
    #pragma unroll
    for (int i = 0; i < 4; i++) {
        int qs_ = qseg[qb + i];
        size_t rowbase = ((size_t)h * TOTAL + (q0 + qb + i)) * TOTAL;
        #pragma unroll
        for (int j = 0; j < 4; j++) {
            float val = (qs_ == kseg[kb + j]) ? acc[i][j] * scale : -1e30f;
            S[rowbase + (k0 + kb + j)] = val;
        }
    }
}

// ---------------------------------------------------------------------------
// Row softmax over [seg_start, seg_end) only.
// ---------------------------------------------------------------------------
__global__ void __launch_bounds__(128) softmax_kernel(
    const int* __restrict__ cu, float* __restrict__ S)
{
    const int qi = blockIdx.x;
    const int h  = blockIdx.y;
    __shared__ __align__(16) int   scu[NCU];
    __shared__ __align__(16) float redmax[4], redsum[4];

    const int tid = threadIdx.x;
    if (tid < NCU) scu[tid] = cu[tid];
    __syncthreads();

    const int s  = segid_of(scu, qi);
    const int qs = scu[s], qe = scu[s + 1];
    const int len = qe - qs;
    float* row = S + ((size_t)h * TOTAL + qi) * TOTAL + qs;

    float v[16];
    const int n = (len + 127) >> 7;
    float m = -1e30f;
    for (int i = 0; i < n; i++) {
        int idx = i * 128 + tid;
        v[i] = (idx < len) ? row[idx] : -1e30f;
        m = fmaxf(m, v[i]);
    }
    #pragma unroll
    for (int off = 16; off; off >>= 1)
        m = fmaxf(m, __shfl_xor_sync(0xffffffffu, m, off));
    if ((tid & 31) == 0) redmax[tid >> 5] = m;
    __syncthreads();
    m = fmaxf(fmaxf(redmax[0], redmax[1]), fmaxf(redmax[2], redmax[3]));

    float sum = 0.f;
    for (int i = 0; i < n; i++) {
        int idx = i * 128 + tid;
        v[i] = (idx < len) ? __expf(v[i] - m) : 0.f;
        sum += v[i];
    }
    #pragma unroll
    for (int off = 16; off; off >>= 1)
        sum += __shfl_xor_sync(0xffffffffu, sum, off);
    if ((tid & 31) == 0) redsum[tid >> 5] = sum;
    __syncthreads();
    sum = redsum[0] + redsum[1] + redsum[2] + redsum[3];

    const float inv = 1.0f / sum;
    for (int i = 0; i < n; i++) {
        int idx = i * 128 + tid;
        if (idx < len) row[idx] = v[i] * inv;
    }
}

// ---------------------------------------------------------------------------
// ctx[q, h*64+d] = sum_k P[h][q][k] * V[k, h*64+d], k restricted to q's segment.
// ---------------------------------------------------------------------------
__global__ void __launch_bounds__(256) pv_kernel(
    const float* __restrict__ S, const float* __restrict__ v,
    const int* __restrict__ cu, float* __restrict__ ctx)
{
    const int h  = blockIdx.y;
    const int q0 = blockIdx.x * 64;

    __shared__ __align__(16) int   scu[NCU];
    __shared__ __align__(16) int   qseg[64], kseg[32];
    __shared__ __align__(16) float Ps[64][33];
    __shared__ __align__(16) float Vs[32][64];

    const int tid = threadIdx.x;
    if (tid < NCU) scu[tid] = cu[tid];
    __syncthreads();

    if (tid < 64) qseg[tid] = segid_of(scu, q0 + tid);
    const int s_lo = segid_of(scu, q0);
    const int s_hi = segid_of(scu, q0 + 63);
    const int ustart = scu[s_lo];
    const int uend   = scu[s_hi + 1];

    const int qb = (tid >> 4) * 4;
    const int db = (tid & 15) * 4;
    float acc[4][4];
    #pragma unroll
    for (int i = 0; i < 4; i++)
        #pragma unroll
        for (int j = 0; j < 4; j++) acc[i][j] = 0.f;

    for (int kb = (ustart / 32) * 32; kb < uend; kb += 32) {
        __syncthreads();
        if (tid < 32) kseg[tid] = segid_of(scu, kb + tid);
        __syncthreads();

        #pragma unroll
        for (int l = 0; l < 2; l++) {
            int fi = tid + l * 256;
            int r  = fi >> 3;
            int c4 = (fi & 7) << 2;
            float4 p4 = *(const float4*)(S + ((size_t)h * TOTAL + (q0 + r)) * TOTAL + kb + c4);
            int qg = qseg[r];
            Ps[r][c4 + 0] = (kseg[c4 + 0] == qg) ? p4.x : 0.f;
            Ps[r][c4 + 1] = (kseg[c4 + 1] == qg) ? p4.y : 0.f;
            Ps[r][c4 + 2] = (kseg[c4 + 2] == qg) ? p4.z : 0.f;
            Ps[r][c4 + 3] = (kseg[c4 + 3] == qg) ? p4.w : 0.f;
        }
        #pragma unroll
        for (int l = 0; l < 2; l++) {
            int fi = tid + l * 256;
            int r  = fi >> 4;
            int c4 = (fi & 15) << 2;
            *(float4*)&Vs[r][c4] =
                *(const float4*)(v + (size_t)(kb + r) * HIDDEN + h * DH + c4);
        }
        __syncthreads();

        #pragma unroll 8
        for (int kk = 0; kk < 32; kk++) {
            float4 rv = *(const float4*)&Vs[kk][db];
            float rp[4];
            #pragma unroll
            for (int i = 0; i < 4; i++) rp[i] = Ps[qb + i][kk];
            #pragma unroll
            for (int i = 0; i < 4; i++) {
                acc[i][0] = fmaf(rp[i], rv.x, acc[i][0]);
                acc[i][1] = fmaf(rp[i], rv.y, acc[i][1]);
                acc[i][2] = fmaf(rp[i], rv.z, acc[i][2]);
                acc[i][3] = fmaf(rp[i], rv.w, acc[i][3]);
            }
        }
    }

    #pragma unroll
    for (int i = 0; i < 4; i++)
        #pragma unroll
        for (int j = 0; j < 4; j++)
            ctx[(size_t)(q0 + qb + i) * HIDDEN + h * DH + db + j] = acc[i][j];
}

// ---------------------------------------------------------------------------
extern "C" void kernel_launch(void* const* d_in, const int* in_sizes, int n_in,
                              void* d_out, int out_size)
{
    (void)in_sizes; (void)n_in; (void)out_size;
    const float* x  = (const float*)d_in[0];
    const int*   cu = (const int*)d_in[1];
    const float* Wq = (const float*)d_in[2];
    const float* bq = (const float*)d_in[3];
    const float* Wk = (const float*)d_in[4];
    const float* bk = (const float*)d_in[5];
    const float* Wv = (const float*)d_in[6];
    const float* bv = (const float*)d_in[7];
    const float* Wo = (const float*)d_in[8];
    const float* bo = (const float*)d_in[9];
    float* out = (float*)d_out;

    float *q, *k, *v, *ctx, *S;
    cudaGetSymbolAddress((void**)&q,   g_q);
    cudaGetSymbolAddress((void**)&k,   g_k);
    cudaGetSymbolAddress((void**)&v,   g_v);
    cudaGetSymbolAddress((void**)&ctx, g_ctx);
    cudaGetSymbolAddress((void**)&S,   g_S);

    dim3 gGrid(HIDDEN / 128, TOTAL / 128);   // (8, 16)
    gemm_tf32_nt_bias<<<gGrid, 256>>>(x, Wq, bq, q, TOTAL, HIDDEN, HIDDEN);
    gemm_tf32_nt_bias<<<gGrid, 256>>>(x, Wk, bk, k, TOTAL, HIDDEN, HIDDEN);
    gemm_tf32_nt_bias<<<gGrid, 256>>>(x, Wv, bv, v, TOTAL, HIDDEN, HIDDEN);

    dim3 sGrid(TOTAL / 64, TOTAL / 64, NHEAD);   // (32, 32, 16)
    scores_kernel<<<sGrid, 256>>>(q, k, cu, S);

    softmax_kernel<<<dim3(TOTAL, NHEAD), 128>>>(cu, S);

    pv_kernel<<<dim3(TOTAL / 64, NHEAD), 256>>>(S, v, cu, ctx);

    gemm_tf32_nt_bias<<<gGrid, 256>>>(ctx, Wo, bo, out, TOTAL, HIDDEN, HIDDEN);
}

// round 8
// speedup vs baseline: 3.0791x; 1.6358x over previous
#include <cuda_runtime.h>
#include <math.h>
#include <stdint.h>

#define TOTAL  2048
#define HIDDEN 1024
#define NHEAD  16
#define DH     64
#define NSEG   8
#define NCU    9
#define LOG2E  1.4426950408889634f

// Scratch (static device arrays — no allocation inside kernel_launch).
__device__ __align__(256) float g_q[TOTAL * HIDDEN];
__device__ __align__(256) float g_k[TOTAL * HIDDEN];
__device__ __align__(256) float g_v[TOTAL * HIDDEN];
__device__ __align__(256) float g_ctx[TOTAL * HIDDEN];

__device__ __forceinline__ int segid_of(const int* scu, int t) {
    int s = 0;
    #pragma unroll
    for (int i = 0; i < NSEG - 1; i++) {
        if (scu[s + 1] <= t) s++;
    }
    return s;
}

__device__ __forceinline__ uint32_t f2tf32(float f) {
    uint32_t u;
    asm("cvt.rna.tf32.f32 %0, %1;" : "=r"(u) : "f"(f));
    return u;
}

__device__ __forceinline__ void mma_tf32(
    float& d0, float& d1, float& d2, float& d3,
    uint32_t a0, uint32_t a1, uint32_t a2, uint32_t a3,
    uint32_t b0, uint32_t b1)
{
    asm volatile(
        "mma.sync.aligned.m16n8k8.row.col.f32.tf32.tf32.f32 "
        "{%0,%1,%2,%3}, {%4,%5,%6,%7}, {%8,%9}, {%0,%1,%2,%3};"
        : "+f"(d0), "+f"(d1), "+f"(d2), "+f"(d3)
        : "r"(a0), "r"(a1), "r"(a2), "r"(a3), "r"(b0), "r"(b1));
}

// ---------------------------------------------------------------------------
// C[M,N] = A[M,K] @ B[N,K]^T + bias[N] using tf32 tensor cores.
// 128x128 block tile, BK=16, 256 threads (8 warps: 2 in M x 4 in N).
// ---------------------------------------------------------------------------
__global__ void __launch_bounds__(256) gemm_tf32_nt_bias(
    const float* __restrict__ A, const float* __restrict__ B,
    const float* __restrict__ bias, float* __restrict__ C,
    int M, int N, int K)
{
    __shared__ __align__(16) float As[128][20];
    __shared__ __align__(16) float Bs[128][20];

    const int tid  = threadIdx.x;
    const int lane = tid & 31;
    const int wid  = tid >> 5;
    const int wm   = (wid & 1) * 64;
    const int wn   = (wid >> 1) * 32;
    const int row0 = blockIdx.y * 128;
    const int col0 = blockIdx.x * 128;

    const int g  = lane >> 2;
    const int t4 = lane & 3;

    float acc[4][4][4];
    #pragma unroll
    for (int i = 0; i < 4; i++)
        #pragma unroll
        for (int j = 0; j < 4; j++)
            #pragma unroll
            for (int f = 0; f < 4; f++) acc[i][j][f] = 0.f;

    const int lr = tid >> 2;
    const int lk = (tid & 3) << 2;

    const float* Arow0 = A + (size_t)(row0 + lr) * K + lk;
    const float* Arow1 = A + (size_t)(row0 + lr + 64) * K + lk;
    const float* Brow0 = B + (size_t)(col0 + lr) * K + lk;
    const float* Brow1 = B + (size_t)(col0 + lr + 64) * K + lk;

    for (int k0 = 0; k0 < K; k0 += 16) {
        float4 a0v = *(const float4*)(Arow0 + k0);
        float4 a1v = *(const float4*)(Arow1 + k0);
        float4 b0v = *(const float4*)(Brow0 + k0);
        float4 b1v = *(const float4*)(Brow1 + k0);
        __syncthreads();
        {
            float4 s;
            s.x = __uint_as_float(f2tf32(a0v.x)); s.y = __uint_as_float(f2tf32(a0v.y));
            s.z = __uint_as_float(f2tf32(a0v.z)); s.w = __uint_as_float(f2tf32(a0v.w));
            *(float4*)&As[lr][lk] = s;
            s.x = __uint_as_float(f2tf32(a1v.x)); s.y = __uint_as_float(f2tf32(a1v.y));
            s.z = __uint_as_float(f2tf32(a1v.z)); s.w = __uint_as_float(f2tf32(a1v.w));
            *(float4*)&As[lr + 64][lk] = s;
            s.x = __uint_as_float(f2tf32(b0v.x)); s.y = __uint_as_float(f2tf32(b0v.y));
            s.z = __uint_as_float(f2tf32(b0v.z)); s.w = __uint_as_float(f2tf32(b0v.w));
            *(float4*)&Bs[lr][lk] = s;
            s.x = __uint_as_float(f2tf32(b1v.x)); s.y = __uint_as_float(f2tf32(b1v.y));
            s.z = __uint_as_float(f2tf32(b1v.z)); s.w = __uint_as_float(f2tf32(b1v.w));
            *(float4*)&Bs[lr + 64][lk] = s;
        }
        __syncthreads();

        #pragma unroll
        for (int kk = 0; kk < 16; kk += 8) {
            uint32_t af[4][4];
            #pragma unroll
            for (int mi = 0; mi < 4; mi++) {
                int r = wm + mi * 16;
                af[mi][0] = __float_as_uint(As[r + g     ][kk + t4    ]);
                af[mi][1] = __float_as_uint(As[r + g + 8 ][kk + t4    ]);
                af[mi][2] = __float_as_uint(As[r + g     ][kk + t4 + 4]);
                af[mi][3] = __float_as_uint(As[r + g + 8 ][kk + t4 + 4]);
            }
            uint32_t bf[4][2];
            #pragma unroll
            for (int ni = 0; ni < 4; ni++) {
                int n = wn + ni * 8;
                bf[ni][0] = __float_as_uint(Bs[n + g][kk + t4    ]);
                bf[ni][1] = __float_as_uint(Bs[n + g][kk + t4 + 4]);
            }
            #pragma unroll
            for (int mi = 0; mi < 4; mi++)
                #pragma unroll
                for (int ni = 0; ni < 4; ni++)
                    mma_tf32(acc[mi][ni][0], acc[mi][ni][1], acc[mi][ni][2], acc[mi][ni][3],
                             af[mi][0], af[mi][1], af[mi][2], af[mi][3],
                             bf[ni][0], bf[ni][1]);
        }
    }

    #pragma unroll
    for (int ni = 0; ni < 4; ni++) {
        int c = col0 + wn + ni * 8 + 2 * t4;
        float2 bv = *(const float2*)(bias + c);
        #pragma unroll
        for (int mi = 0; mi < 4; mi++) {
            int r = row0 + wm + mi * 16 + g;
            float2 v0 = make_float2(acc[mi][ni][0] + bv.x, acc[mi][ni][1] + bv.y);
            float2 v1 = make_float2(acc[mi][ni][2] + bv.x, acc[mi][ni][3] + bv.y);
            *(float2*)(C + (size_t)r * N + c)       = v0;
            *(float2*)(C + (size_t)(r + 8) * N + c) = v1;
        }
    }
}

// ---------------------------------------------------------------------------
// Fused flash attention with block-diagonal (segment) masking.
// Grid: (TOTAL/64, NHEAD). 128 threads = 4 warps; warp w owns q rows
// [q0+16w, q0+16w+16). Online softmax, tf32 mma for QK^T and PV.
// K SMEM buffer is reused for the P tile between the two MMAs.
// ---------------------------------------------------------------------------
__global__ void __launch_bounds__(128) flash_attn_kernel(
    const float* __restrict__ q, const float* __restrict__ k,
    const float* __restrict__ v, const int* __restrict__ cu,
    float* __restrict__ ctx)
{
    const int h  = blockIdx.y;
    const int q0 = blockIdx.x * 64;

    __shared__ __align__(16) int   scu[NCU];
    __shared__ __align__(16) int   ksegS[64];
    __shared__ __align__(16) float Ks[64][68];   // K tile, later aliased as P tile
    __shared__ __align__(16) float Vs[64][68];   // V tile, [k][d] natural

    const int tid  = threadIdx.x;
    const int lane = tid & 31;
    const int w    = tid >> 5;      // 0..3
    const int wm   = w * 16;
    const int g    = lane >> 2;     // 0..7
    const int t4   = lane & 3;      // 0..3

    if (tid < NCU) scu[tid] = cu[tid];
    __syncthreads();

    // ---- load Q tile (scaled by 1/sqrt(dh)) into Ks, pull fragments to regs
    {
        const int r0 = tid >> 4;          // 0..7
        const int c4 = (tid & 15) * 4;    // 0..60
        #pragma unroll
        for (int i = 0; i < 8; i++) {
            int r = r0 + i * 8;
            float4 t = *(const float4*)(q + (size_t)(q0 + r) * HIDDEN + h * DH + c4);
            float4 s;
            s.x = __uint_as_float(f2tf32(t.x * 0.125f));
            s.y = __uint_as_float(f2tf32(t.y * 0.125f));
            s.z = __uint_as_float(f2tf32(t.z * 0.125f));
            s.w = __uint_as_float(f2tf32(t.w * 0.125f));
            *(float4*)&Ks[r][c4] = s;
        }
    }
    __syncthreads();

    uint32_t qf[8][4];
    #pragma unroll
    for (int kk = 0; kk < 8; kk++) {
        qf[kk][0] = __float_as_uint(Ks[wm + g     ][kk * 8 + t4    ]);
        qf[kk][1] = __float_as_uint(Ks[wm + g + 8 ][kk * 8 + t4    ]);
        qf[kk][2] = __float_as_uint(Ks[wm + g     ][kk * 8 + t4 + 4]);
        qf[kk][3] = __float_as_uint(Ks[wm + g + 8 ][kk * 8 + t4 + 4]);
    }

    const int qs0 = segid_of(scu, q0 + wm + g);
    const int qs1 = segid_of(scu, q0 + wm + g + 8);
    const int s_lo = segid_of(scu, q0);
    const int s_hi = segid_of(scu, q0 + 63);
    const int ustart = scu[s_lo];
    const int uend   = scu[s_hi + 1];

    float m0 = -1e30f, m1 = -1e30f, l0 = 0.f, l1 = 0.f;
    float of[8][4];
    #pragma unroll
    for (int ni = 0; ni < 8; ni++)
        #pragma unroll
        for (int f = 0; f < 4; f++) of[ni][f] = 0.f;

    __syncthreads();   // done reading Q from Ks

    for (int kb = (ustart / 64) * 64; kb < uend; kb += 64) {
        // ---- load K and V tiles (tf32)
        {
            const int r0 = tid >> 4;
            const int c4 = (tid & 15) * 4;
            #pragma unroll
            for (int i = 0; i < 8; i++) {
                int r = r0 + i * 8;
                float4 tk = *(const float4*)(k + (size_t)(kb + r) * HIDDEN + h * DH + c4);
                float4 tv = *(const float4*)(v + (size_t)(kb + r) * HIDDEN + h * DH + c4);
                float4 s;
                s.x = __uint_as_float(f2tf32(tk.x)); s.y = __uint_as_float(f2tf32(tk.y));
                s.z = __uint_as_float(f2tf32(tk.z)); s.w = __uint_as_float(f2tf32(tk.w));
                *(float4*)&Ks[r][c4] = s;
                s.x = __uint_as_float(f2tf32(tv.x)); s.y = __uint_as_float(f2tf32(tv.y));
                s.z = __uint_as_float(f2tf32(tv.z)); s.w = __uint_as_float(f2tf32(tv.w));
                *(float4*)&Vs[r][c4] = s;
            }
            if (tid < 64) ksegS[tid] = segid_of(scu, kb + tid);
        }
        __syncthreads();

        // ---- S = Q K^T (scaled already)
        float sf[8][4];
        #pragma unroll
        for (int ni = 0; ni < 8; ni++)
            #pragma unroll
            for (int f = 0; f < 4; f++) sf[ni][f] = 0.f;

        #pragma unroll
        for (int kk = 0; kk < 8; kk++) {
            #pragma unroll
            for (int ni = 0; ni < 8; ni++) {
                uint32_t b0 = __float_as_uint(Ks[ni * 8 + g][kk * 8 + t4    ]);
                uint32_t b1 = __float_as_uint(Ks[ni * 8 + g][kk * 8 + t4 + 4]);
                mma_tf32(sf[ni][0], sf[ni][1], sf[ni][2], sf[ni][3],
                         qf[kk][0], qf[kk][1], qf[kk][2], qf[kk][3], b0, b1);
            }
        }

        // ---- mask + row max
        float rmax0 = -1e30f, rmax1 = -1e30f;
        #pragma unroll
        for (int ni = 0; ni < 8; ni++) {
            int col = ni * 8 + 2 * t4;
            int ks0 = ksegS[col], ks1 = ksegS[col + 1];
            sf[ni][0] = (ks0 == qs0) ? sf[ni][0] : -1e30f;
            sf[ni][1] = (ks1 == qs0) ? sf[ni][1] : -1e30f;
            sf[ni][2] = (ks0 == qs1) ? sf[ni][2] : -1e30f;
            sf[ni][3] = (ks1 == qs1) ? sf[ni][3] : -1e30f;
            rmax0 = fmaxf(rmax0, fmaxf(sf[ni][0], sf[ni][1]));
            rmax1 = fmaxf(rmax1, fmaxf(sf[ni][2], sf[ni][3]));
        }
        rmax0 = fmaxf(rmax0, __shfl_xor_sync(0xffffffffu, rmax0, 1));
        rmax0 = fmaxf(rmax0, __shfl_xor_sync(0xffffffffu, rmax0, 2));
        rmax1 = fmaxf(rmax1, __shfl_xor_sync(0xffffffffu, rmax1, 1));
        rmax1 = fmaxf(rmax1, __shfl_xor_sync(0xffffffffu, rmax1, 2));

        float mn0 = fmaxf(m0, rmax0);
        float mn1 = fmaxf(m1, rmax1);
        float a0 = exp2f((m0 - mn0) * LOG2E);
        float a1 = exp2f((m1 - mn1) * LOG2E);

        float rs0 = 0.f, rs1 = 0.f;
        #pragma unroll
        for (int ni = 0; ni < 8; ni++) {
            float p0 = exp2f((sf[ni][0] - mn0) * LOG2E);
            float p1 = exp2f((sf[ni][1] - mn0) * LOG2E);
            float p2 = exp2f((sf[ni][2] - mn1) * LOG2E);
            float p3 = exp2f((sf[ni][3] - mn1) * LOG2E);
            rs0 += p0 + p1;
            rs1 += p2 + p3;
            sf[ni][0] = p0; sf[ni][1] = p1; sf[ni][2] = p2; sf[ni][3] = p3;
            of[ni][0] *= a0; of[ni][1] *= a0; of[ni][2] *= a1; of[ni][3] *= a1;
        }
        rs0 += __shfl_xor_sync(0xffffffffu, rs0, 1);
        rs0 += __shfl_xor_sync(0xffffffffu, rs0, 2);
        rs1 += __shfl_xor_sync(0xffffffffu, rs1, 1);
        rs1 += __shfl_xor_sync(0xffffffffu, rs1, 2);
        l0 = l0 * a0 + rs0;
        l1 = l1 * a1 + rs1;
        m0 = mn0; m1 = mn1;

        __syncthreads();   // all warps done reading K from Ks

        // ---- P -> Ks (aliased), tf32
        #pragma unroll
        for (int ni = 0; ni < 8; ni++) {
            int col = ni * 8 + 2 * t4;
            Ks[wm + g     ][col    ] = __uint_as_float(f2tf32(sf[ni][0]));
            Ks[wm + g     ][col + 1] = __uint_as_float(f2tf32(sf[ni][1]));
            Ks[wm + g + 8 ][col    ] = __uint_as_float(f2tf32(sf[ni][2]));
            Ks[wm + g + 8 ][col + 1] = __uint_as_float(f2tf32(sf[ni][3]));
        }
        __syncthreads();

        // ---- O += P V
        #pragma unroll
        for (int kk = 0; kk < 8; kk++) {
            uint32_t af0 = __float_as_uint(Ks[wm + g     ][kk * 8 + t4    ]);
            uint32_t af1 = __float_as_uint(Ks[wm + g + 8 ][kk * 8 + t4    ]);
            uint32_t af2 = __float_as_uint(Ks[wm + g     ][kk * 8 + t4 + 4]);
            uint32_t af3 = __float_as_uint(Ks[wm + g + 8 ][kk * 8 + t4 + 4]);
            #pragma unroll
            for (int ni = 0; ni < 8; ni++) {
                uint32_t b0 = __float_as_uint(Vs[kk * 8 + t4    ][ni * 8 + g]);
                uint32_t b1 = __float_as_uint(Vs[kk * 8 + t4 + 4][ni * 8 + g]);
                mma_tf32(of[ni][0], of[ni][1], of[ni][2], of[ni][3],
                         af0, af1, af2, af3, b0, b1);
            }
        }
        __syncthreads();   // before next tile overwrites Ks/Vs
    }

    // ---- write out ctx
    const float inv0 = 1.0f / l0;
    const float inv1 = 1.0f / l1;
    #pragma unroll
    for (int ni = 0; ni < 8; ni++) {
        int col = h * DH + ni * 8 + 2 * t4;
        int r0 = q0 + wm + g;
        *(float2*)(ctx + (size_t)r0 * HIDDEN + col) =
            make_float2(of[ni][0] * inv0, of[ni][1] * inv0);
        *(float2*)(ctx + (size_t)(r0 + 8) * HIDDEN + col) =
            make_float2(of[ni][2] * inv1, of[ni][3] * inv1);
    }
}

// ---------------------------------------------------------------------------
extern "C" void kernel_launch(void* const* d_in, const int* in_sizes, int n_in,
                              void* d_out, int out_size)
{
    (void)in_sizes; (void)n_in; (void)out_size;
    const float* x  = (const float*)d_in[0];
    const int*   cu = (const int*)d_in[1];
    const float* Wq = (const float*)d_in[2];
    const float* bq = (const float*)d_in[3];
    const float* Wk = (const float*)d_in[4];
    const float* bk = (const float*)d_in[5];
    const float* Wv = (const float*)d_in[6];
    const float* bv = (const float*)d_in[7];
    const float* Wo = (const float*)d_in[8];
    const float* bo = (const float*)d_in[9];
    float* out = (float*)d_out;

    float *q, *k, *v, *ctx;
    cudaGetSymbolAddress((void**)&q,   g_q);
    cudaGetSymbolAddress((void**)&k,   g_k);
    cudaGetSymbolAddress((void**)&v,   g_v);
    cudaGetSymbolAddress((void**)&ctx, g_ctx);

    dim3 gGrid(HIDDEN / 128, TOTAL / 128);   // (8, 16)
    gemm_tf32_nt_bias<<<gGrid, 256>>>(x, Wq, bq, q, TOTAL, HIDDEN, HIDDEN);
    gemm_tf32_nt_bias<<<gGrid, 256>>>(x, Wk, bk, k, TOTAL, HIDDEN, HIDDEN);
    gemm_tf32_nt_bias<<<gGrid, 256>>>(x, Wv, bv, v, TOTAL, HIDDEN, HIDDEN);

    flash_attn_kernel<<<dim3(TOTAL / 64, NHEAD), 128>>>(q, k, v, cu, ctx);

    gemm_tf32_nt_bias<<<gGrid, 256>>>(ctx, Wo, bo, out, TOTAL, HIDDEN, HIDDEN);
}

// round 9
// speedup vs baseline: 3.4151x; 1.1091x over previous
#include <cuda_runtime.h>
#include <math.h>
#include <stdint.h>

#define TOTAL  2048
#define HIDDEN 1024
#define NHEAD  16
#define DH     64
#define NSEG   8
#define NCU    9
#define LOG2E  1.4426950408889634f

// Scratch (static device arrays — no allocation inside kernel_launch).
__device__ __align__(256) float g_q[TOTAL * HIDDEN];
__device__ __align__(256) float g_k[TOTAL * HIDDEN];
__device__ __align__(256) float g_v[TOTAL * HIDDEN];
__device__ __align__(256) float g_ctx[TOTAL * HIDDEN];

__device__ __forceinline__ int segid_of(const int* scu, int t) {
    int s = 0;
    #pragma unroll
    for (int i = 0; i < NSEG - 1; i++) {
        if (scu[s + 1] <= t) s++;
    }
    return s;
}

__device__ __forceinline__ uint32_t f2tf32(float f) {
    uint32_t u;
    asm("cvt.rna.tf32.f32 %0, %1;" : "=r"(u) : "f"(f));
    return u;
}

__device__ __forceinline__ void mma_tf32(
    float& d0, float& d1, float& d2, float& d3,
    uint32_t a0, uint32_t a1, uint32_t a2, uint32_t a3,
    uint32_t b0, uint32_t b1)
{
    asm volatile(
        "mma.sync.aligned.m16n8k8.row.col.f32.tf32.tf32.f32 "
        "{%0,%1,%2,%3}, {%4,%5,%6,%7}, {%8,%9}, {%0,%1,%2,%3};"
        : "+f"(d0), "+f"(d1), "+f"(d2), "+f"(d3)
        : "r"(a0), "r"(a1), "r"(a2), "r"(a3), "r"(b0), "r"(b1));
}

__device__ __forceinline__ void cp16(void* smem, const void* g) {
    uint32_t s = (uint32_t)__cvta_generic_to_shared(smem);
    asm volatile("cp.async.ca.shared.global [%0], [%1], 16;" :: "r"(s), "l"(g));
}
__device__ __forceinline__ void cp_commit() {
    asm volatile("cp.async.commit_group;");
}
__device__ __forceinline__ void cp_wait0() {
    asm volatile("cp.async.wait_group 0;");
}

// ---------------------------------------------------------------------------
// Triple-GEMM: C_z[M,N] = A[M,K] @ W_z[N,K]^T + b_z[N], z = blockIdx.z.
// 128x128 tile, BK=16, 256 threads, cp.async 2-stage double buffering,
// tf32 mma.m16n8k8 (cvt at fragment-load time).
// ---------------------------------------------------------------------------
__global__ void __launch_bounds__(256) gemm3_tf32_nt_bias(
    const float* __restrict__ A,
    const float* __restrict__ W0, const float* __restrict__ b0, float* __restrict__ C0,
    const float* __restrict__ W1, const float* __restrict__ b1, float* __restrict__ C1,
    const float* __restrict__ W2, const float* __restrict__ b2, float* __restrict__ C2,
    int M, int N, int K)
{
    const float* B; const float* bias; float* C;
    if (blockIdx.z == 0)      { B = W0; bias = b0; C = C0; }
    else if (blockIdx.z == 1) { B = W1; bias = b1; C = C1; }
    else                      { B = W2; bias = b2; C = C2; }

    __shared__ __align__(16) float As[2][128][20];
    __shared__ __align__(16) float Bs[2][128][20];

    const int tid  = threadIdx.x;
    const int lane = tid & 31;
    const int wid  = tid >> 5;
    const int wm   = (wid & 1) * 64;
    const int wn   = (wid >> 1) * 32;
    const int row0 = blockIdx.y * 128;
    const int col0 = blockIdx.x * 128;

    const int g  = lane >> 2;
    const int t4 = lane & 3;

    float acc[4][4][4];
    #pragma unroll
    for (int i = 0; i < 4; i++)
        #pragma unroll
        for (int j = 0; j < 4; j++)
            #pragma unroll
            for (int f = 0; f < 4; f++) acc[i][j][f] = 0.f;

    // load mapping: 2 threads per row, each thread 2 float4 (8 floats)
    const int lr = tid >> 1;          // 0..127
    const int lc = (tid & 1) * 8;     // 0 or 8

    const float* Arow = A + (size_t)(row0 + lr) * K + lc;
    const float* Brow = B + (size_t)(col0 + lr) * K + lc;

    // prologue: stage 0
    cp16(&As[0][lr][lc],     Arow);
    cp16(&As[0][lr][lc + 4], Arow + 4);
    cp16(&Bs[0][lr][lc],     Brow);
    cp16(&Bs[0][lr][lc + 4], Brow + 4);
    cp_commit();

    for (int k0 = 0; k0 < K; k0 += 16) {
        const int st = (k0 >> 4) & 1;
        cp_wait0();
        __syncthreads();

        if (k0 + 16 < K) {
            const float* An = Arow + k0 + 16;
            const float* Bn = Brow + k0 + 16;
            cp16(&As[st ^ 1][lr][lc],     An);
            cp16(&As[st ^ 1][lr][lc + 4], An + 4);
            cp16(&Bs[st ^ 1][lr][lc],     Bn);
            cp16(&Bs[st ^ 1][lr][lc + 4], Bn + 4);
            cp_commit();
        }

        #pragma unroll
        for (int kk = 0; kk < 16; kk += 8) {
            uint32_t af[4][4];
            #pragma unroll
            for (int mi = 0; mi < 4; mi++) {
                int r = wm + mi * 16;
                af[mi][0] = f2tf32(As[st][r + g     ][kk + t4    ]);
                af[mi][1] = f2tf32(As[st][r + g + 8 ][kk + t4    ]);
                af[mi][2] = f2tf32(As[st][r + g     ][kk + t4 + 4]);
                af[mi][3] = f2tf32(As[st][r + g + 8 ][kk + t4 + 4]);
            }
            uint32_t bf[4][2];
            #pragma unroll
            for (int ni = 0; ni < 4; ni++) {
                int n = wn + ni * 8;
                bf[ni][0] = f2tf32(Bs[st][n + g][kk + t4    ]);
                bf[ni][1] = f2tf32(Bs[st][n + g][kk + t4 + 4]);
            }
            #pragma unroll
            for (int mi = 0; mi < 4; mi++)
                #pragma unroll
                for (int ni = 0; ni < 4; ni++)
                    mma_tf32(acc[mi][ni][0], acc[mi][ni][1], acc[mi][ni][2], acc[mi][ni][3],
                             af[mi][0], af[mi][1], af[mi][2], af[mi][3],
                             bf[ni][0], bf[ni][1]);
        }
    }

    #pragma unroll
    for (int ni = 0; ni < 4; ni++) {
        int c = col0 + wn + ni * 8 + 2 * t4;
        float2 bv = *(const float2*)(bias + c);
        #pragma unroll
        for (int mi = 0; mi < 4; mi++) {
            int r = row0 + wm + mi * 16 + g;
            float2 v0 = make_float2(acc[mi][ni][0] + bv.x, acc[mi][ni][1] + bv.y);
            float2 v1 = make_float2(acc[mi][ni][2] + bv.x, acc[mi][ni][3] + bv.y);
            *(float2*)(C + (size_t)r * N + c)       = v0;
            *(float2*)(C + (size_t)(r + 8) * N + c) = v1;
        }
    }
}

// ---------------------------------------------------------------------------
// Fused flash attention with block-diagonal (segment) masking.
// Grid: (TOTAL/64, NHEAD). 128 threads = 4 warps; warp w owns q rows
// [q0+16w, q0+16w+16). Online softmax, tf32 mma for QK^T and PV.
// ---------------------------------------------------------------------------
__global__ void __launch_bounds__(128) flash_attn_kernel(
    const float* __restrict__ q, const float* __restrict__ k,
    const float* __restrict__ v, const int* __restrict__ cu,
    float* __restrict__ ctx)
{
    const int h  = blockIdx.y;
    const int q0 = blockIdx.x * 64;

    __shared__ __align__(16) int   scu[NCU];
    __shared__ __align__(16) int   ksegS[64];
    __shared__ __align__(16) float Ks[64][68];   // K tile, later aliased as P tile
    __shared__ __align__(16) float Vs[64][68];   // V tile, [k][d] natural

    const int tid  = threadIdx.x;
    const int lane = tid & 31;
    const int w    = tid >> 5;
    const int wm   = w * 16;
    const int g    = lane >> 2;
    const int t4   = lane & 3;

    if (tid < NCU) scu[tid] = cu[tid];
    __syncthreads();

    {
        const int r0 = tid >> 4;
        const int c4 = (tid & 15) * 4;
        #pragma unroll
        for (int i = 0; i < 8; i++) {
            int r = r0 + i * 8;
            float4 t = *(const float4*)(q + (size_t)(q0 + r) * HIDDEN + h * DH + c4);
            float4 s;
            s.x = __uint_as_float(f2tf32(t.x * 0.125f));
            s.y = __uint_as_float(f2tf32(t.y * 0.125f));
            s.z = __uint_as_float(f2tf32(t.z * 0.125f));
            s.w = __uint_as_float(f2tf32(t.w * 0.125f));
            *(float4*)&Ks[r][c4] = s;
        }
    }
    __syncthreads();

    uint32_t qf[8][4];
    #pragma unroll
    for (int kk = 0; kk < 8; kk++) {
        qf[kk][0] = __float_as_uint(Ks[wm + g     ][kk * 8 + t4    ]);
        qf[kk][1] = __float_as_uint(Ks[wm + g + 8 ][kk * 8 + t4    ]);
        qf[kk][2] = __float_as_uint(Ks[wm + g     ][kk * 8 + t4 + 4]);
        qf[kk][3] = __float_as_uint(Ks[wm + g + 8 ][kk * 8 + t4 + 4]);
    }

    const int qs0 = segid_of(scu, q0 + wm + g);
    const int qs1 = segid_of(scu, q0 + wm + g + 8);
    const int s_lo = segid_of(scu, q0);
    const int s_hi = segid_of(scu, q0 + 63);
    const int ustart = scu[s_lo];
    const int uend   = scu[s_hi + 1];

    float m0 = -1e30f, m1 = -1e30f, l0 = 0.f, l1 = 0.f;
    float of[8][4];
    #pragma unroll
    for (int ni = 0; ni < 8; ni++)
        #pragma unroll
        for (int f = 0; f < 4; f++) of[ni][f] = 0.f;

    __syncthreads();

    for (int kb = (ustart / 64) * 64; kb < uend; kb += 64) {
        {
            const int r0 = tid >> 4;
            const int c4 = (tid & 15) * 4;
            #pragma unroll
            for (int i = 0; i < 8; i++) {
                int r = r0 + i * 8;
                float4 tk = *(const float4*)(k + (size_t)(kb + r) * HIDDEN + h * DH + c4);
                float4 tv = *(const float4*)(v + (size_t)(kb + r) * HIDDEN + h * DH + c4);
                float4 s;
                s.x = __uint_as_float(f2tf32(tk.x)); s.y = __uint_as_float(f2tf32(tk.y));
                s.z = __uint_as_float(f2tf32(tk.z)); s.w = __uint_as_float(f2tf32(tk.w));
                *(float4*)&Ks[r][c4] = s;
                s.x = __uint_as_float(f2tf32(tv.x)); s.y = __uint_as_float(f2tf32(tv.y));
                s.z = __uint_as_float(f2tf32(tv.z)); s.w = __uint_as_float(f2tf32(tv.w));
                *(float4*)&Vs[r][c4] = s;
            }
            if (tid < 64) ksegS[tid] = segid_of(scu, kb + tid);
        }
        __syncthreads();

        float sf[8][4];
        #pragma unroll
        for (int ni = 0; ni < 8; ni++)
            #pragma unroll
            for (int f = 0; f < 4; f++) sf[ni][f] = 0.f;

        #pragma unroll
        for (int kk = 0; kk < 8; kk++) {
            #pragma unroll
            for (int ni = 0; ni < 8; ni++) {
                uint32_t b0 = __float_as_uint(Ks[ni * 8 + g][kk * 8 + t4    ]);
                uint32_t b1 = __float_as_uint(Ks[ni * 8 + g][kk * 8 + t4 + 4]);
                mma_tf32(sf[ni][0], sf[ni][1], sf[ni][2], sf[ni][3],
                         qf[kk][0], qf[kk][1], qf[kk][2], qf[kk][3], b0, b1);
            }
        }

        float rmax0 = -1e30f, rmax1 = -1e30f;
        #pragma unroll
        for (int ni = 0; ni < 8; ni++) {
            int col = ni * 8 + 2 * t4;
            int ks0 = ksegS[col], ks1 = ksegS[col + 1];
            sf[ni][0] = (ks0 == qs0) ? sf[ni][0] : -1e30f;
            sf[ni][1] = (ks1 == qs0) ? sf[ni][1] : -1e30f;
            sf[ni][2] = (ks0 == qs1) ? sf[ni][2] : -1e30f;
            sf[ni][3] = (ks1 == qs1) ? sf[ni][3] : -1e30f;
            rmax0 = fmaxf(rmax0, fmaxf(sf[ni][0], sf[ni][1]));
            rmax1 = fmaxf(rmax1, fmaxf(sf[ni][2], sf[ni][3]));
        }
        rmax0 = fmaxf(rmax0, __shfl_xor_sync(0xffffffffu, rmax0, 1));
        rmax0 = fmaxf(rmax0, __shfl_xor_sync(0xffffffffu, rmax0, 2));
        rmax1 = fmaxf(rmax1, __shfl_xor_sync(0xffffffffu, rmax1, 1));
        rmax1 = fmaxf(rmax1, __shfl_xor_sync(0xffffffffu, rmax1, 2));

        float mn0 = fmaxf(m0, rmax0);
        float mn1 = fmaxf(m1, rmax1);
        float a0 = exp2f((m0 - mn0) * LOG2E);
        float a1 = exp2f((m1 - mn1) * LOG2E);

        float rs0 = 0.f, rs1 = 0.f;
        #pragma unroll
        for (int ni = 0; ni < 8; ni++) {
            float p0 = exp2f((sf[ni][0] - mn0) * LOG2E);
            float p1 = exp2f((sf[ni][1] - mn0) * LOG2E);
            float p2 = exp2f((sf[ni][2] - mn1) * LOG2E);
            float p3 = exp2f((sf[ni][3] - mn1) * LOG2E);
            rs0 += p0 + p1;
            rs1 += p2 + p3;
            sf[ni][0] = p0; sf[ni][1] = p1; sf[ni][2] = p2; sf[ni][3] = p3;
            of[ni][0] *= a0; of[ni][1] *= a0; of[ni][2] *= a1; of[ni][3] *= a1;
        }
        rs0 += __shfl_xor_sync(0xffffffffu, rs0, 1);
        rs0 += __shfl_xor_sync(0xffffffffu, rs0, 2);
        rs1 += __shfl_xor_sync(0xffffffffu, rs1, 1);
        rs1 += __shfl_xor_sync(0xffffffffu, rs1, 2);
        l0 = l0 * a0 + rs0;
        l1 = l1 * a1 + rs1;
        m0 = mn0; m1 = mn1;

        __syncthreads();

        #pragma unroll
        for (int ni = 0; ni < 8; ni++) {
            int col = ni * 8 + 2 * t4;
            Ks[wm + g     ][col    ] = __uint_as_float(f2tf32(sf[ni][0]));
            Ks[wm + g     ][col + 1] = __uint_as_float(f2tf32(sf[ni][1]));
            Ks[wm + g + 8 ][col    ] = __uint_as_float(f2tf32(sf[ni][2]));
            Ks[wm + g + 8 ][col + 1] = __uint_as_float(f2tf32(sf[ni][3]));
        }
        __syncthreads();

        #pragma unroll
        for (int kk = 0; kk < 8; kk++) {
            uint32_t af0 = __float_as_uint(Ks[wm + g     ][kk * 8 + t4    ]);
            uint32_t af1 = __float_as_uint(Ks[wm + g + 8 ][kk * 8 + t4    ]);
            uint32_t af2 = __float_as_uint(Ks[wm + g     ][kk * 8 + t4 + 4]);
            uint32_t af3 = __float_as_uint(Ks[wm + g + 8 ][kk * 8 + t4 + 4]);
            #pragma unroll
            for (int ni = 0; ni < 8; ni++) {
                uint32_t b0 = __float_as_uint(Vs[kk * 8 + t4    ][ni * 8 + g]);
                uint32_t b1 = __float_as_uint(Vs[kk * 8 + t4 + 4][ni * 8 + g]);
                mma_tf32(of[ni][0], of[ni][1], of[ni][2], of[ni][3],
                         af0, af1, af2, af3, b0, b1);
            }
        }
        __syncthreads();
    }

    const float inv0 = 1.0f / l0;
    const float inv1 = 1.0f / l1;
    #pragma unroll
    for (int ni = 0; ni < 8; ni++) {
        int col = h * DH + ni * 8 + 2 * t4;
        int r0 = q0 + wm + g;
        *(float2*)(ctx + (size_t)r0 * HIDDEN + col) =
            make_float2(of[ni][0] * inv0, of[ni][1] * inv0);
        *(float2*)(ctx + (size_t)(r0 + 8) * HIDDEN + col) =
            make_float2(of[ni][2] * inv1, of[ni][3] * inv1);
    }
}

// ---------------------------------------------------------------------------
extern "C" void kernel_launch(void* const* d_in, const int* in_sizes, int n_in,
                              void* d_out, int out_size)
{
    (void)in_sizes; (void)n_in; (void)out_size;
    const float* x  = (const float*)d_in[0];
    const int*   cu = (const int*)d_in[1];
    const float* Wq = (const float*)d_in[2];
    const float* bq = (const float*)d_in[3];
    const float* Wk = (const float*)d_in[4];
    const float* bk = (const float*)d_in[5];
    const float* Wv = (const float*)d_in[6];
    const float* bv = (const float*)d_in[7];
    const float* Wo = (const float*)d_in[8];
    const float* bo = (const float*)d_in[9];
    float* out = (float*)d_out;

    float *q, *k, *v, *ctx;
    cudaGetSymbolAddress((void**)&q,   g_q);
    cudaGetSymbolAddress((void**)&k,   g_k);
    cudaGetSymbolAddress((void**)&v,   g_v);
    cudaGetSymbolAddress((void**)&ctx, g_ctx);

    // Fused QKV projections (z selects the weight/bias/output triple)
    dim3 qkvGrid(HIDDEN / 128, TOTAL / 128, 3);
    gemm3_tf32_nt_bias<<<qkvGrid, 256>>>(x,
                                         Wq, bq, q,
                                         Wk, bk, k,
                                         Wv, bv, v,
                                         TOTAL, HIDDEN, HIDDEN);

    flash_attn_kernel<<<dim3(TOTAL / 64, NHEAD), 128>>>(q, k, v, cu, ctx);

    // Output projection (single z slice)
    dim3 oGrid(HIDDEN / 128, TOTAL / 128, 1);
    gemm3_tf32_nt_bias<<<oGrid, 256>>>(ctx,
                                       Wo, bo, out,
                                       Wo, bo, out,
                                       Wo, bo, out,
                                       TOTAL, HIDDEN, HIDDEN);
}